// round 14
// baseline (speedup 1.0000x reference)
#include <cuda_runtime.h>
#include <cuda_bf16.h>
#include <stdint.h>
#include <math_constants.h>

// Problem shape (fixed)
#define D   512
#define BQ  4096
#define KA  32768
#define H_ELEMS (BQ * D)
#define A_ELEMS (KA * D)

// GEMM tiling (R7 geometry, s8 elements): CTA 128x128, K-tile 64 bytes, 2-stage
#define BM 128
#define BN 128
#define BK 64                              // s8 elems per k-tile (= 64 bytes/row)
#define NKT (D / BK)                       // 8
#define ROWB 80                            // 64B data + 16B pad per smem row
#define STAGE_BYTES (BM * ROWB)            // 10240 per operand per stage
#define WTILES (KA / 32)                   // 1024 (32-col tiles per row)
#define MARGIN 0.25f                       // > 2 x 6-sigma int8 score error

// Device scratch
__device__ int8_t g_Hq[H_ELEMS];           // h quantized s8 (per-row scale)
__device__ int8_t g_Aq[A_ELEMS];           // a/||a|| quantized s8 (per-row scale)
__device__ float g_sc_h[BQ];               // h row scales
__device__ float g_sc_a[KA];               // A row scales (include 1/||a||)
__device__ float g_inv_a[KA];              // exact 1/||a|| for fp32 rescore
__device__ uint4 g_cand[(size_t)BQ * WTILES];

// ---------------------------------------------------------------------------
// Quantize h rows: one warp per row. scale = max|h|/127.
// ---------------------------------------------------------------------------
__global__ void k_prep_h(const float* __restrict__ H) {
    int r = (blockIdx.x * blockDim.x + threadIdx.x) >> 5;
    int lane = threadIdx.x & 31;
    if (r >= BQ) return;
    const float4* row = (const float4*)(H + (size_t)r * D);
    float4 v[4]; float mx = 0.f;
#pragma unroll
    for (int i = 0; i < 4; i++) {
        v[i] = row[lane + 32 * i];
        mx = fmaxf(mx, fmaxf(fmaxf(fabsf(v[i].x), fabsf(v[i].y)),
                             fmaxf(fabsf(v[i].z), fabsf(v[i].w))));
    }
#pragma unroll
    for (int o = 16; o; o >>= 1) mx = fmaxf(mx, __shfl_xor_sync(0xffffffffu, mx, o));
    mx = fmaxf(mx, 1e-20f);
    float q = 127.0f / mx;
    if (lane == 0) g_sc_h[r] = mx / 127.0f;
    unsigned* dst = (unsigned*)(g_Hq + (size_t)r * D);
#pragma unroll
    for (int i = 0; i < 4; i++) {
        int b0 = __float2int_rn(v[i].x * q), b1 = __float2int_rn(v[i].y * q);
        int b2 = __float2int_rn(v[i].z * q), b3 = __float2int_rn(v[i].w * q);
        dst[lane + 32 * i] = (unsigned)(b0 & 0xFF) | ((unsigned)(b1 & 0xFF) << 8)
                           | ((unsigned)(b2 & 0xFF) << 16) | ((unsigned)(b3 & 0xFF) << 24);
    }
}

// ---------------------------------------------------------------------------
// Normalize + quantize A rows: one warp per row. scale = max|a/||a|||/127.
// ---------------------------------------------------------------------------
__global__ void k_prep_a(const float* __restrict__ A) {
    int r = (blockIdx.x * blockDim.x + threadIdx.x) >> 5;
    int lane = threadIdx.x & 31;
    if (r >= KA) return;
    const float4* row = (const float4*)(A + (size_t)r * D);
    float4 v[4]; float s = 0.f, mx = 0.f;
#pragma unroll
    for (int i = 0; i < 4; i++) {
        v[i] = row[lane + 32 * i];
        s += v[i].x * v[i].x + v[i].y * v[i].y + v[i].z * v[i].z + v[i].w * v[i].w;
        mx = fmaxf(mx, fmaxf(fmaxf(fabsf(v[i].x), fabsf(v[i].y)),
                             fmaxf(fabsf(v[i].z), fabsf(v[i].w))));
    }
#pragma unroll
    for (int o = 16; o; o >>= 1) {
        s += __shfl_xor_sync(0xffffffffu, s, o);
        mx = fmaxf(mx, __shfl_xor_sync(0xffffffffu, mx, o));
    }
    float inv = 1.0f / fmaxf(sqrtf(s), 1e-8f);
    float mhat = fmaxf(mx * inv, 1e-20f);      // max|a_i|/||a||
    float q = 127.0f / mhat;                   // quant: round(a_i*inv*q)
    if (lane == 0) { g_inv_a[r] = inv; g_sc_a[r] = mhat / 127.0f; }
    float qi = inv * q;
    unsigned* dst = (unsigned*)(g_Aq + (size_t)r * D);
#pragma unroll
    for (int i = 0; i < 4; i++) {
        int b0 = __float2int_rn(v[i].x * qi), b1 = __float2int_rn(v[i].y * qi);
        int b2 = __float2int_rn(v[i].z * qi), b3 = __float2int_rn(v[i].w * qi);
        dst[lane + 32 * i] = (unsigned)(b0 & 0xFF) | ((unsigned)(b1 & 0xFF) << 8)
                           | ((unsigned)(b2 & 0xFF) << 16) | ((unsigned)(b3 & 0xFF) << 24);
    }
}

// ---------------------------------------------------------------------------
// int8 tensor-core GEMM + top-2 per (row, 32-col warp tile).
// Exact R7 schedule: 128x128 CTA, 2-stage cp.async, warps 2(m) x 4(n),
// warp tile 64x32, mma.m16n8k32.s8 (2048 MACs/instr, 2x bf16 rate).
// ---------------------------------------------------------------------------
#define MMAS8(d, a, b) asm volatile( \
    "mma.sync.aligned.m16n8k32.row.col.s32.s8.s8.s32 " \
    "{%0,%1,%2,%3}, {%4,%5,%6,%7}, {%8,%9}, {%0,%1,%2,%3};" \
    : "+r"(d[0]), "+r"(d[1]), "+r"(d[2]), "+r"(d[3]) \
    : "r"(a[0]), "r"(a[1]), "r"(a[2]), "r"(a[3]), "r"(b[0]), "r"(b[1]))

__global__ __launch_bounds__(256, 2) void k_gemm_s8() {
    __shared__ int8_t sH[2 * STAGE_BYTES];
    __shared__ int8_t sA[2 * STAGE_BYTES];

    int t = threadIdx.x;
    int m0 = blockIdx.y * BM, n0 = blockIdx.x * BN;
    int lane = t & 31, warp = t >> 5;
    int wm = warp >> 2, wn = warp & 3;          // 2 x 4 warp grid
    int lrow = lane >> 2, lcol = lane & 3;

    unsigned sHb = (unsigned)__cvta_generic_to_shared(sH);
    unsigned sAb = (unsigned)__cvta_generic_to_shared(sA);

    // Loader (R7 mapping): lr = row 0..63 (+64), lu = 16B seg within 64B chunk
    int lr = t >> 2, lu = t & 3;
    const char* gh0 = (const char*)(g_Hq + (size_t)(m0 + lr) * D) + lu * 16;
    const char* gh1 = (const char*)(g_Hq + (size_t)(m0 + lr + 64) * D) + lu * 16;
    const char* ga0 = (const char*)(g_Aq + (size_t)(n0 + lr) * D) + lu * 16;
    const char* ga1 = (const char*)(g_Aq + (size_t)(n0 + lr + 64) * D) + lu * 16;
    unsigned sd0 = (unsigned)(lr * ROWB + lu * 16);
    unsigned sd1 = (unsigned)((lr + 64) * ROWB + lu * 16);

    // ldmatrix offsets (same formulas as proven R7, now in bytes directly)
    unsigned offA = (unsigned)((wm * 64 + (lane & 15)) * ROWB + (lane >> 4) * 16);
    unsigned offB = (unsigned)((wn * 32 + (lane & 7)) * ROWB + ((lane >> 3) & 1) * 16);

    int acc[4][4][4];
#pragma unroll
    for (int mi = 0; mi < 4; mi++)
#pragma unroll
        for (int ni = 0; ni < 4; ni++)
#pragma unroll
            for (int c = 0; c < 4; c++) acc[mi][ni][c] = 0;

    auto issue = [&](int kt, int st) {
        unsigned hb = sHb + st * STAGE_BYTES;
        unsigned ab = sAb + st * STAGE_BYTES;
        const char* h0 = gh0 + kt * BK;
        const char* h1 = gh1 + kt * BK;
        const char* a0 = ga0 + kt * BK;
        const char* a1 = ga1 + kt * BK;
        asm volatile("cp.async.cg.shared.global [%0], [%1], 16;" :: "r"(hb + sd0), "l"(h0) : "memory");
        asm volatile("cp.async.cg.shared.global [%0], [%1], 16;" :: "r"(hb + sd1), "l"(h1) : "memory");
        asm volatile("cp.async.cg.shared.global [%0], [%1], 16;" :: "r"(ab + sd0), "l"(a0) : "memory");
        asm volatile("cp.async.cg.shared.global [%0], [%1], 16;" :: "r"(ab + sd1), "l"(a1) : "memory");
    };

    issue(0, 0);
    asm volatile("cp.async.commit_group;" ::: "memory");

    for (int kt = 0; kt < NKT; kt++) {
        asm volatile("cp.async.wait_group 0;" ::: "memory");
        __syncthreads();
        if (kt + 1 < NKT) issue(kt + 1, (kt + 1) & 1);
        asm volatile("cp.async.commit_group;" ::: "memory");

        unsigned hb = sHb + (kt & 1) * STAGE_BYTES;
        unsigned ab = sAb + (kt & 1) * STAGE_BYTES;
#pragma unroll
        for (int kf = 0; kf < 2; kf++) {        // 2 x k32 per 64B tile
            unsigned a[4][4], b[4][2];
#pragma unroll
            for (int mi = 0; mi < 4; mi++) {
                unsigned ad = hb + offA + (unsigned)(mi * 16 * ROWB) + kf * 32;
                asm volatile("ldmatrix.sync.aligned.m8n8.x4.shared.b16 {%0,%1,%2,%3}, [%4];"
                             : "=r"(a[mi][0]), "=r"(a[mi][1]), "=r"(a[mi][2]), "=r"(a[mi][3])
                             : "r"(ad));
            }
#pragma unroll
            for (int ni = 0; ni < 4; ni++) {
                unsigned bd = ab + offB + (unsigned)(ni * 8 * ROWB) + kf * 32;
                asm volatile("ldmatrix.sync.aligned.m8n8.x2.shared.b16 {%0,%1}, [%2];"
                             : "=r"(b[ni][0]), "=r"(b[ni][1])
                             : "r"(bd));
            }
#pragma unroll
            for (int mi = 0; mi < 4; mi++)
#pragma unroll
                for (int ni = 0; ni < 4; ni++)
                    MMAS8(acc[mi][ni], a[mi], b[ni]);
        }
    }

    // Epilogue: rescale to true units (sc_h[row] * sc_a[col]), top-2 per
    // (row, 32-col warp tile), 4-lane shuffle merge, store. (R7-proven flow.)
    float sca[4][2];
#pragma unroll
    for (int ni = 0; ni < 4; ni++)
#pragma unroll
        for (int c = 0; c < 2; c++)
            sca[ni][c] = g_sc_a[n0 + wn * 32 + ni * 8 + lcol * 2 + c];

#pragma unroll
    for (int mi = 0; mi < 4; mi++)
#pragma unroll
        for (int h = 0; h < 2; h++) {
            int rg = m0 + wm * 64 + mi * 16 + lrow + h * 8;
            float sch = g_sc_h[rg];
            float s1 = -CUDART_INF_F, s2 = -CUDART_INF_F;
            unsigned i1 = 0, i2 = 0;
#pragma unroll
            for (int ni = 0; ni < 4; ni++)
#pragma unroll
                for (int c = 0; c < 2; c++) {
                    float v = (float)acc[mi][ni][h * 2 + c] * sch * sca[ni][c];
                    unsigned n = (unsigned)(n0 + wn * 32 + ni * 8 + lcol * 2 + c);
                    if (v > s1) { s2 = s1; i2 = i1; s1 = v; i1 = n; }
                    else if (v > s2) { s2 = v; i2 = n; }
                }
#pragma unroll
            for (int off = 1; off <= 2; off <<= 1) {
                float t1 = __shfl_xor_sync(0xffffffffu, s1, off);
                unsigned j1 = __shfl_xor_sync(0xffffffffu, i1, off);
                float t2 = __shfl_xor_sync(0xffffffffu, s2, off);
                unsigned j2 = __shfl_xor_sync(0xffffffffu, i2, off);
                if (t1 > s1) {
                    float os = s1; unsigned oi = i1;
                    s1 = t1; i1 = j1;
                    if (t2 > os) { s2 = t2; i2 = j2; } else { s2 = os; i2 = oi; }
                } else if (t1 > s2) { s2 = t1; i2 = j1; }
            }
            if (lcol == 0)
                g_cand[(size_t)rg * WTILES + (size_t)(blockIdx.x * 4 + wn)] =
                    make_uint4(__float_as_uint(s1), i1, __float_as_uint(s2), i2);
        }
}

// ---------------------------------------------------------------------------
// Per row: approx max over 2048 candidates, fp32-rescore within MARGIN,
// exact argmax (first-index tie-break). One warp per row. (Proven code.)
// ---------------------------------------------------------------------------
__global__ void k_select(const float* __restrict__ H, const float* __restrict__ A,
                         float* __restrict__ out) {
    int r = (blockIdx.x * blockDim.x + threadIdx.x) >> 5;
    int lane = threadIdx.x & 31;
    if (r >= BQ) return;
    const uint2* cand = (const uint2*)(g_cand + (size_t)r * WTILES);  // 2048 entries

    float mx = -CUDART_INF_F;
    for (int j = lane; j < WTILES * 2; j += 32)
        mx = fmaxf(mx, __uint_as_float(cand[j].x));
#pragma unroll
    for (int o = 16; o; o >>= 1) mx = fmaxf(mx, __shfl_xor_sync(0xffffffffu, mx, o));
    float thr = mx - MARGIN;

    const float4* h4 = (const float4*)(H + (size_t)r * D);
    float4 hv[4];
#pragma unroll
    for (int i = 0; i < 4; i++) hv[i] = h4[lane + 32 * i];

    unsigned long long best = 0ull;
    for (int j0 = 0; j0 < WTILES * 2; j0 += 32) {
        uint2 c = cand[j0 + lane];
        unsigned m = __ballot_sync(0xffffffffu, __uint_as_float(c.x) >= thr);
        while (m) {
            int src = __ffs(m) - 1; m &= m - 1;
            unsigned idx = __shfl_sync(0xffffffffu, c.y, src);
            const float4* a4 = (const float4*)(A + (size_t)idx * D);
            float p = 0.f;
#pragma unroll
            for (int i = 0; i < 4; i++) {
                float4 av = a4[lane + 32 * i];
                p += hv[i].x * av.x + hv[i].y * av.y + hv[i].z * av.z + hv[i].w * av.w;
            }
#pragma unroll
            for (int o = 16; o; o >>= 1) p += __shfl_xor_sync(0xffffffffu, p, o);
            float s = p * g_inv_a[idx];
            unsigned u = __float_as_uint(s);
            u = (u & 0x80000000u) ? ~u : (u | 0x80000000u);
            unsigned long long key =
                ((unsigned long long)u << 32) | (unsigned long long)(0xFFFFFFFFu - idx);
            if (key > best) best = key;
        }
    }
    if (lane == 0)
        out[r] = (float)(0xFFFFFFFFu - (unsigned)(best & 0xFFFFFFFFull));
}

// ---------------------------------------------------------------------------
extern "C" void kernel_launch(void* const* d_in, const int* in_sizes, int n_in,
                              void* d_out, int out_size) {
    const float* H = (const float*)d_in[0];
    const float* A = (const float*)d_in[1];
    if (n_in >= 2 && in_sizes[0] == A_ELEMS) {   // bind by size
        H = (const float*)d_in[1];
        A = (const float*)d_in[0];
    }

    k_prep_h<<<BQ / 8, 256>>>(H);                // warp per row
    k_prep_a<<<KA / 8, 256>>>(A);                // warp per row

    dim3 grid(KA / BN, BQ / BM);                 // 256 x 32 = 8192 CTAs
    k_gemm_s8<<<grid, 256>>>();

    k_select<<<BQ / 8, 256>>>(H, A, (float*)d_out);
}

// round 15
// speedup vs baseline: 2.2124x; 2.2124x over previous
#include <cuda_runtime.h>
#include <cuda_bf16.h>
#include <stdint.h>
#include <math_constants.h>

// Problem shape (fixed)
#define D   512
#define BQ  4096
#define KA  32768
#define H_ELEMS (BQ * D)
#define A_ELEMS (KA * D)

// GEMM tiling (R7-proven): CTA 128x128, K-tile 32, 2-stage cp.async, 256 thr
#define BM 128
#define BN 128
#define BK 32
#define SSTRIDE 40                       // halves per smem row (32 + 8 pad)
#define STAGE_HALVES (BM * SSTRIDE)      // 5120
#define STAGE_BYTES  (STAGE_HALVES * 2)  // 10240
#define NKT (D / BK)                     // 16
#define CTILES (KA / 128)                // 256 CTA-col tiles per row
#define MARGIN 0.15f                     // >> 2 * 8-sigma bf16 score error

// Device scratch
__device__ __nv_bfloat16 g_Hb[H_ELEMS];
__device__ __nv_bfloat16 g_Ab[A_ELEMS];          // A scaled by 1/||a||
__device__ float g_inv_a[KA];
__device__ uint4 g_cand[(size_t)BQ * CTILES];    // top-2 per (row, 128-col tile)

// ---------------------------------------------------------------------------
__global__ void k_prep_h(const float* __restrict__ H) {
    int i = blockIdx.x * blockDim.x + threadIdx.x;
    float2 v = ((const float2*)H)[i];
    __nv_bfloat162 p = __floats2bfloat162_rn(v.x, v.y);
    ((unsigned*)g_Hb)[i] = *(unsigned*)&p;
}

__global__ void k_prep_a(const float* __restrict__ A) {
    int gw = (blockIdx.x * blockDim.x + threadIdx.x) >> 5;
    int lane = threadIdx.x & 31;
    if (gw >= KA) return;
    const float4* row = (const float4*)(A + (size_t)gw * D);
    float4 v[4]; float s = 0.f;
#pragma unroll
    for (int i = 0; i < 4; i++) {
        v[i] = row[lane + 32 * i];
        s += v[i].x * v[i].x + v[i].y * v[i].y + v[i].z * v[i].z + v[i].w * v[i].w;
    }
#pragma unroll
    for (int o = 16; o; o >>= 1) s += __shfl_xor_sync(0xffffffffu, s, o);
    float inv = 1.0f / fmaxf(sqrtf(s), 1e-8f);
    if (lane == 0) g_inv_a[gw] = inv;
    unsigned* dst = (unsigned*)(g_Ab + (size_t)gw * D);
#pragma unroll
    for (int i = 0; i < 4; i++) {
        __nv_bfloat162 p0 = __floats2bfloat162_rn(v[i].x * inv, v[i].y * inv);
        __nv_bfloat162 p1 = __floats2bfloat162_rn(v[i].z * inv, v[i].w * inv);
        int e = lane + 32 * i;
        dst[2 * e]     = *(unsigned*)&p0;
        dst[2 * e + 1] = *(unsigned*)&p1;
    }
}

// ---------------------------------------------------------------------------
#define MMA16816(d, a, b0, b1) asm volatile( \
    "mma.sync.aligned.m16n8k16.row.col.f32.bf16.bf16.f32 " \
    "{%0,%1,%2,%3}, {%4,%5,%6,%7}, {%8,%9}, {%0,%1,%2,%3};" \
    : "+f"(d[0]), "+f"(d[1]), "+f"(d[2]), "+f"(d[3]) \
    : "r"(a[0]), "r"(a[1]), "r"(a[2]), "r"(a[3]), "r"(b0), "r"(b1))

__global__ __launch_bounds__(256, 2) void k_gemm_bf16() {
    __shared__ __nv_bfloat16 sH[2 * STAGE_HALVES];
    __shared__ __nv_bfloat16 sA[2 * STAGE_HALVES];
    __shared__ uint4 smerge[BM][4];              // cross-warp top-2 staging (8KB)

    int t = threadIdx.x;
    int m0 = blockIdx.y * BM, n0 = blockIdx.x * BN;
    int lane = t & 31, warp = t >> 5;
    int wm = warp >> 2, wn = warp & 3;           // 2 x 4 warp grid
    int lrow = lane >> 2, lcol = lane & 3;

    unsigned sHb = (unsigned)__cvta_generic_to_shared(sH);
    unsigned sAb = (unsigned)__cvta_generic_to_shared(sA);

    // Loader (R7-proven): each thread cp.asyncs 2x16B from H and 2x16B from A
    int lr = t >> 2, lu = t & 3;
    const __nv_bfloat16* gh0 = g_Hb + (size_t)(m0 + lr) * D + lu * 8;
    const __nv_bfloat16* gh1 = g_Hb + (size_t)(m0 + lr + 64) * D + lu * 8;
    const __nv_bfloat16* ga0 = g_Ab + (size_t)(n0 + lr) * D + lu * 8;
    const __nv_bfloat16* ga1 = g_Ab + (size_t)(n0 + lr + 64) * D + lu * 8;
    unsigned sd0 = (unsigned)(lr * SSTRIDE + lu * 8) * 2;
    unsigned sd1 = (unsigned)((lr + 64) * SSTRIDE + lu * 8) * 2;

    // ldmatrix per-lane byte offsets (R7 formulas; offB's lane pattern already
    // generates the x4 addressing: lanes 16-31 -> rows +8)
    unsigned offA = (unsigned)((wm * 64 + (lane & 15)) * SSTRIDE + ((lane >> 4) * 8)) * 2;
    unsigned offB = (unsigned)((wn * 32 + (lane & 7) + ((lane >> 4) * 8)) * SSTRIDE
                               + (((lane >> 3) & 1) * 8)) * 2;

    float acc[4][4][4];
#pragma unroll
    for (int mi = 0; mi < 4; mi++)
#pragma unroll
        for (int ni = 0; ni < 4; ni++)
#pragma unroll
            for (int c = 0; c < 4; c++) acc[mi][ni][c] = 0.f;

    auto issue = [&](int kt, int st) {
        unsigned hb = sHb + st * STAGE_BYTES;
        unsigned ab = sAb + st * STAGE_BYTES;
        const __nv_bfloat16* h0 = gh0 + kt * BK;
        const __nv_bfloat16* h1 = gh1 + kt * BK;
        const __nv_bfloat16* a0 = ga0 + kt * BK;
        const __nv_bfloat16* a1 = ga1 + kt * BK;
        asm volatile("cp.async.cg.shared.global [%0], [%1], 16;" :: "r"(hb + sd0), "l"(h0) : "memory");
        asm volatile("cp.async.cg.shared.global [%0], [%1], 16;" :: "r"(hb + sd1), "l"(h1) : "memory");
        asm volatile("cp.async.cg.shared.global [%0], [%1], 16;" :: "r"(ab + sd0), "l"(a0) : "memory");
        asm volatile("cp.async.cg.shared.global [%0], [%1], 16;" :: "r"(ab + sd1), "l"(a1) : "memory");
    };

    issue(0, 0);
    asm volatile("cp.async.commit_group;" ::: "memory");

    for (int kt = 0; kt < NKT; kt++) {
        asm volatile("cp.async.wait_group 0;" ::: "memory");
        __syncthreads();
        if (kt + 1 < NKT) issue(kt + 1, (kt + 1) & 1);
        asm volatile("cp.async.commit_group;" ::: "memory");

        unsigned hb = sHb + (kt & 1) * STAGE_BYTES;
        unsigned ab = sAb + (kt & 1) * STAGE_BYTES;
#pragma unroll
        for (int kf = 0; kf < 2; kf++) {
            unsigned a[4][4], b[2][4];
#pragma unroll
            for (int mi = 0; mi < 4; mi++) {
                unsigned ad = hb + offA + (unsigned)(mi * 16 * SSTRIDE) * 2 + kf * 32;
                asm volatile("ldmatrix.sync.aligned.m8n8.x4.shared.b16 {%0,%1,%2,%3}, [%4];"
                             : "=r"(a[mi][0]), "=r"(a[mi][1]), "=r"(a[mi][2]), "=r"(a[mi][3])
                             : "r"(ad));
            }
            // B: 2 x ldmatrix.x4, each covers 2 n8-tiles (halves B LDSM count)
#pragma unroll
            for (int nj = 0; nj < 2; nj++) {
                unsigned bd = ab + offB + (unsigned)(nj * 16 * SSTRIDE) * 2 + kf * 32;
                asm volatile("ldmatrix.sync.aligned.m8n8.x4.shared.b16 {%0,%1,%2,%3}, [%4];"
                             : "=r"(b[nj][0]), "=r"(b[nj][1]), "=r"(b[nj][2]), "=r"(b[nj][3])
                             : "r"(bd));
            }
#pragma unroll
            for (int mi = 0; mi < 4; mi++)
#pragma unroll
                for (int nj = 0; nj < 2; nj++) {
                    MMA16816(acc[mi][2 * nj],     a[mi], b[nj][0], b[nj][1]);
                    MMA16816(acc[mi][2 * nj + 1], a[mi], b[nj][2], b[nj][3]);
                }
        }
    }

    // ---- Epilogue stage 1 (R7-proven): per (row, 32-col warp tile) top-2 ----
#pragma unroll
    for (int mi = 0; mi < 4; mi++)
#pragma unroll
        for (int h = 0; h < 2; h++) {
            float s1 = -CUDART_INF_F, s2 = -CUDART_INF_F;
            unsigned i1 = 0, i2 = 0;
#pragma unroll
            for (int ni = 0; ni < 4; ni++)
#pragma unroll
                for (int c = 0; c < 2; c++) {
                    float v = acc[mi][ni][h * 2 + c];
                    unsigned n = (unsigned)(n0 + wn * 32 + ni * 8 + lcol * 2 + c);
                    if (v > s1) { s2 = s1; i2 = i1; s1 = v; i1 = n; }
                    else if (v > s2) { s2 = v; i2 = n; }
                }
#pragma unroll
            for (int off = 1; off <= 2; off <<= 1) {
                float t1 = __shfl_xor_sync(0xffffffffu, s1, off);
                unsigned j1 = __shfl_xor_sync(0xffffffffu, i1, off);
                float t2 = __shfl_xor_sync(0xffffffffu, s2, off);
                unsigned j2 = __shfl_xor_sync(0xffffffffu, i2, off);
                if (t1 > s1) {
                    float os = s1; unsigned oi = i1;
                    s1 = t1; i1 = j1;
                    if (t2 > os) { s2 = t2; i2 = j2; } else { s2 = os; i2 = oi; }
                } else if (t1 > s2) { s2 = t1; i2 = j1; }
            }
            if (lcol == 0) {
                int rl = wm * 64 + mi * 16 + h * 8 + lrow;   // local row 0..127
                smerge[rl][wn] = make_uint4(__float_as_uint(s1), i1,
                                            __float_as_uint(s2), i2);
            }
        }

    // ---- Epilogue stage 2: merge 4 wn-tiles -> top-2 per (row, 128-col) ----
    __syncthreads();
    if (t < BM) {
        float s1 = -CUDART_INF_F, s2 = -CUDART_INF_F;
        unsigned i1 = 0, i2 = 0;
#pragma unroll
        for (int w = 0; w < 4; w++) {            // ascending n: strict > keeps first idx
            uint4 e = smerge[t][w];
            float a1 = __uint_as_float(e.x), a2 = __uint_as_float(e.z);
            if (a1 > s1) { s2 = s1; i2 = i1; s1 = a1; i1 = e.y; }
            else if (a1 > s2) { s2 = a1; i2 = e.y; }
            if (a2 > s1) { s2 = s1; i2 = i1; s1 = a2; i1 = e.w; }
            else if (a2 > s2) { s2 = a2; i2 = e.w; }
        }
        g_cand[(size_t)(m0 + t) * CTILES + blockIdx.x] =
            make_uint4(__float_as_uint(s1), i1, __float_as_uint(s2), i2);
    }
}

// ---------------------------------------------------------------------------
// Per row: approx max over 512 candidates, fp32-rescore within MARGIN,
// exact argmax (first-index tie-break). One warp per row. (Proven code.)
// ---------------------------------------------------------------------------
__global__ void k_select(const float* __restrict__ H, const float* __restrict__ A,
                         float* __restrict__ out) {
    int r = (blockIdx.x * blockDim.x + threadIdx.x) >> 5;
    int lane = threadIdx.x & 31;
    if (r >= BQ) return;
    const uint2* cand = (const uint2*)(g_cand + (size_t)r * CTILES);  // 512 entries

    float mx = -CUDART_INF_F;
    for (int j = lane; j < CTILES * 2; j += 32)
        mx = fmaxf(mx, __uint_as_float(cand[j].x));
#pragma unroll
    for (int o = 16; o; o >>= 1) mx = fmaxf(mx, __shfl_xor_sync(0xffffffffu, mx, o));
    float thr = mx - MARGIN;

    const float4* h4 = (const float4*)(H + (size_t)r * D);
    float4 hv[4];
#pragma unroll
    for (int i = 0; i < 4; i++) hv[i] = h4[lane + 32 * i];

    unsigned long long best = 0ull;
    for (int j0 = 0; j0 < CTILES * 2; j0 += 32) {
        uint2 c = cand[j0 + lane];
        unsigned m = __ballot_sync(0xffffffffu, __uint_as_float(c.x) >= thr);
        while (m) {
            int src = __ffs(m) - 1; m &= m - 1;
            unsigned idx = __shfl_sync(0xffffffffu, c.y, src);
            const float4* a4 = (const float4*)(A + (size_t)idx * D);
            float p = 0.f;
#pragma unroll
            for (int i = 0; i < 4; i++) {
                float4 av = a4[lane + 32 * i];
                p += hv[i].x * av.x + hv[i].y * av.y + hv[i].z * av.z + hv[i].w * av.w;
            }
#pragma unroll
            for (int o = 16; o; o >>= 1) p += __shfl_xor_sync(0xffffffffu, p, o);
            float s = p * g_inv_a[idx];
            unsigned u = __float_as_uint(s);
            u = (u & 0x80000000u) ? ~u : (u | 0x80000000u);
            unsigned long long key =
                ((unsigned long long)u << 32) | (unsigned long long)(0xFFFFFFFFu - idx);
            if (key > best) best = key;
        }
    }
    if (lane == 0)
        out[r] = (float)(0xFFFFFFFFu - (unsigned)(best & 0xFFFFFFFFull));
}

// ---------------------------------------------------------------------------
extern "C" void kernel_launch(void* const* d_in, const int* in_sizes, int n_in,
                              void* d_out, int out_size) {
    const float* H = (const float*)d_in[0];
    const float* A = (const float*)d_in[1];
    if (n_in >= 2 && in_sizes[0] == A_ELEMS) {   // bind by size
        H = (const float*)d_in[1];
        A = (const float*)d_in[0];
    }

    k_prep_h<<<H_ELEMS / 2 / 256, 256>>>(H);
    k_prep_a<<<KA / 8, 256>>>(A);

    dim3 grid(KA / BN, BQ / BM);                 // 256 x 32 = 8192 CTAs
    k_gemm_bf16<<<grid, 256>>>();

    k_select<<<BQ / 8, 256>>>(H, A, (float*)d_out);
}

// round 16
// speedup vs baseline: 2.2629x; 1.0229x over previous
#include <cuda_runtime.h>
#include <cuda_bf16.h>
#include <stdint.h>
#include <math_constants.h>

// Problem shape (fixed)
#define D   512
#define BQ  4096
#define KA  32768
#define H_ELEMS (BQ * D)
#define A_ELEMS (KA * D)

// GEMM tiling (R14-proven): CTA 128x128, K-tile 32, 256 thr, now 3-stage
#define BM 128
#define BN 128
#define BK 32
#define NSTG 3
#define SSTRIDE 40                       // halves per smem row (32 + 8 pad)
#define STAGE_HALVES (BM * SSTRIDE)      // 5120
#define STAGE_BYTES  (STAGE_HALVES * 2)  // 10240
#define NKT (D / BK)                     // 16
#define CTILES (KA / 128)                // 256 CTA-col tiles per row
#define MARGIN 0.15f                     // >> 2 * 8-sigma bf16 score error

// dynamic smem layout (bytes)
#define SM_H      0                                  // 3 x 10240
#define SM_A      (NSTG * STAGE_BYTES)               // 3 x 10240
#define SM_MERGE  (2 * NSTG * STAGE_BYTES)           // 128 x 4 x 16 = 8192
#define SMEM_TOTAL (SM_MERGE + BM * 4 * 16)          // 69632 -> 2 CTAs/SM

// Device scratch
__device__ __nv_bfloat16 g_Hb[H_ELEMS];
__device__ __nv_bfloat16 g_Ab[A_ELEMS];          // A scaled by 1/||a||
__device__ float g_inv_a[KA];
__device__ uint4 g_cand[(size_t)BQ * CTILES];    // top-2 per (row, 128-col tile)

// ---------------------------------------------------------------------------
__global__ void k_prep_h(const float* __restrict__ H) {
    int i = blockIdx.x * blockDim.x + threadIdx.x;
    float2 v = ((const float2*)H)[i];
    __nv_bfloat162 p = __floats2bfloat162_rn(v.x, v.y);
    ((unsigned*)g_Hb)[i] = *(unsigned*)&p;
}

__global__ void k_prep_a(const float* __restrict__ A) {
    int gw = (blockIdx.x * blockDim.x + threadIdx.x) >> 5;
    int lane = threadIdx.x & 31;
    if (gw >= KA) return;
    const float4* row = (const float4*)(A + (size_t)gw * D);
    float4 v[4]; float s = 0.f;
#pragma unroll
    for (int i = 0; i < 4; i++) {
        v[i] = row[lane + 32 * i];
        s += v[i].x * v[i].x + v[i].y * v[i].y + v[i].z * v[i].z + v[i].w * v[i].w;
    }
#pragma unroll
    for (int o = 16; o; o >>= 1) s += __shfl_xor_sync(0xffffffffu, s, o);
    float inv = 1.0f / fmaxf(sqrtf(s), 1e-8f);
    if (lane == 0) g_inv_a[gw] = inv;
    unsigned* dst = (unsigned*)(g_Ab + (size_t)gw * D);
#pragma unroll
    for (int i = 0; i < 4; i++) {
        __nv_bfloat162 p0 = __floats2bfloat162_rn(v[i].x * inv, v[i].y * inv);
        __nv_bfloat162 p1 = __floats2bfloat162_rn(v[i].z * inv, v[i].w * inv);
        int e = lane + 32 * i;
        dst[2 * e]     = *(unsigned*)&p0;
        dst[2 * e + 1] = *(unsigned*)&p1;
    }
}

// ---------------------------------------------------------------------------
#define MMA16816(d, a, b0, b1) asm volatile( \
    "mma.sync.aligned.m16n8k16.row.col.f32.bf16.bf16.f32 " \
    "{%0,%1,%2,%3}, {%4,%5,%6,%7}, {%8,%9}, {%0,%1,%2,%3};" \
    : "+f"(d[0]), "+f"(d[1]), "+f"(d[2]), "+f"(d[3]) \
    : "r"(a[0]), "r"(a[1]), "r"(a[2]), "r"(a[3]), "r"(b0), "r"(b1))

__global__ __launch_bounds__(256, 2) void k_gemm_bf16() {
    extern __shared__ char smem[];
    unsigned sbase = (unsigned)__cvta_generic_to_shared(smem);
    unsigned sHb = sbase + SM_H;
    unsigned sAb = sbase + SM_A;
    uint4 (*smerge)[4] = (uint4 (*)[4])(smem + SM_MERGE);

    int t = threadIdx.x;
    int m0 = blockIdx.y * BM, n0 = blockIdx.x * BN;
    int lane = t & 31, warp = t >> 5;
    int wm = warp >> 2, wn = warp & 3;           // 2 x 4 warp grid
    int lrow = lane >> 2, lcol = lane & 3;

    // Loader (proven): each thread cp.asyncs 2x16B from H and 2x16B from A
    int lr = t >> 2, lu = t & 3;
    const __nv_bfloat16* gh0 = g_Hb + (size_t)(m0 + lr) * D + lu * 8;
    const __nv_bfloat16* gh1 = g_Hb + (size_t)(m0 + lr + 64) * D + lu * 8;
    const __nv_bfloat16* ga0 = g_Ab + (size_t)(n0 + lr) * D + lu * 8;
    const __nv_bfloat16* ga1 = g_Ab + (size_t)(n0 + lr + 64) * D + lu * 8;
    unsigned sd0 = (unsigned)(lr * SSTRIDE + lu * 8) * 2;
    unsigned sd1 = (unsigned)((lr + 64) * SSTRIDE + lu * 8) * 2;

    // ldmatrix per-lane byte offsets (proven formulas)
    unsigned offA = (unsigned)((wm * 64 + (lane & 15)) * SSTRIDE + ((lane >> 4) * 8)) * 2;
    unsigned offB = (unsigned)((wn * 32 + (lane & 7) + ((lane >> 4) * 8)) * SSTRIDE
                               + (((lane >> 3) & 1) * 8)) * 2;

    float acc[4][4][4];
#pragma unroll
    for (int mi = 0; mi < 4; mi++)
#pragma unroll
        for (int ni = 0; ni < 4; ni++)
#pragma unroll
            for (int c = 0; c < 4; c++) acc[mi][ni][c] = 0.f;

    auto issue = [&](int kt) {
        int st = kt % NSTG;
        unsigned hb = sHb + st * STAGE_BYTES;
        unsigned ab = sAb + st * STAGE_BYTES;
        const __nv_bfloat16* h0 = gh0 + kt * BK;
        const __nv_bfloat16* h1 = gh1 + kt * BK;
        const __nv_bfloat16* a0 = ga0 + kt * BK;
        const __nv_bfloat16* a1 = ga1 + kt * BK;
        asm volatile("cp.async.cg.shared.global [%0], [%1], 16;" :: "r"(hb + sd0), "l"(h0) : "memory");
        asm volatile("cp.async.cg.shared.global [%0], [%1], 16;" :: "r"(hb + sd1), "l"(h1) : "memory");
        asm volatile("cp.async.cg.shared.global [%0], [%1], 16;" :: "r"(ab + sd0), "l"(a0) : "memory");
        asm volatile("cp.async.cg.shared.global [%0], [%1], 16;" :: "r"(ab + sd1), "l"(a1) : "memory");
        asm volatile("cp.async.commit_group;" ::: "memory");
    };

    // Prologue: 2 stages in flight
    issue(0);
    issue(1);

    for (int kt = 0; kt < NKT; kt++) {
        asm volatile("cp.async.wait_group 1;" ::: "memory");   // stage kt ready
        __syncthreads();
        if (kt + 2 < NKT) issue(kt + 2);   // buffer (kt+2)%3 freed by compute kt-1
        else asm volatile("cp.async.commit_group;" ::: "memory");  // keep group count

        unsigned hb = sHb + (kt % NSTG) * STAGE_BYTES;
        unsigned ab = sAb + (kt % NSTG) * STAGE_BYTES;
#pragma unroll
        for (int kf = 0; kf < 2; kf++) {
            unsigned a[4][4], b[2][4];
#pragma unroll
            for (int mi = 0; mi < 4; mi++) {
                unsigned ad = hb + offA + (unsigned)(mi * 16 * SSTRIDE) * 2 + kf * 32;
                asm volatile("ldmatrix.sync.aligned.m8n8.x4.shared.b16 {%0,%1,%2,%3}, [%4];"
                             : "=r"(a[mi][0]), "=r"(a[mi][1]), "=r"(a[mi][2]), "=r"(a[mi][3])
                             : "r"(ad));
            }
#pragma unroll
            for (int nj = 0; nj < 2; nj++) {   // x4: 2 n8-tiles per LDSM
                unsigned bd = ab + offB + (unsigned)(nj * 16 * SSTRIDE) * 2 + kf * 32;
                asm volatile("ldmatrix.sync.aligned.m8n8.x4.shared.b16 {%0,%1,%2,%3}, [%4];"
                             : "=r"(b[nj][0]), "=r"(b[nj][1]), "=r"(b[nj][2]), "=r"(b[nj][3])
                             : "r"(bd));
            }
#pragma unroll
            for (int mi = 0; mi < 4; mi++)
#pragma unroll
                for (int nj = 0; nj < 2; nj++) {
                    MMA16816(acc[mi][2 * nj],     a[mi], b[nj][0], b[nj][1]);
                    MMA16816(acc[mi][2 * nj + 1], a[mi], b[nj][2], b[nj][3]);
                }
        }
    }

    // ---- Epilogue stage 1 (proven): per (row, 32-col warp tile) top-2 ----
#pragma unroll
    for (int mi = 0; mi < 4; mi++)
#pragma unroll
        for (int h = 0; h < 2; h++) {
            float s1 = -CUDART_INF_F, s2 = -CUDART_INF_F;
            unsigned i1 = 0, i2 = 0;
#pragma unroll
            for (int ni = 0; ni < 4; ni++)
#pragma unroll
                for (int c = 0; c < 2; c++) {
                    float v = acc[mi][ni][h * 2 + c];
                    unsigned n = (unsigned)(n0 + wn * 32 + ni * 8 + lcol * 2 + c);
                    if (v > s1) { s2 = s1; i2 = i1; s1 = v; i1 = n; }
                    else if (v > s2) { s2 = v; i2 = n; }
                }
#pragma unroll
            for (int off = 1; off <= 2; off <<= 1) {
                float t1 = __shfl_xor_sync(0xffffffffu, s1, off);
                unsigned j1 = __shfl_xor_sync(0xffffffffu, i1, off);
                float t2 = __shfl_xor_sync(0xffffffffu, s2, off);
                unsigned j2 = __shfl_xor_sync(0xffffffffu, i2, off);
                if (t1 > s1) {
                    float os = s1; unsigned oi = i1;
                    s1 = t1; i1 = j1;
                    if (t2 > os) { s2 = t2; i2 = j2; } else { s2 = os; i2 = oi; }
                } else if (t1 > s2) { s2 = t1; i2 = j1; }
            }
            if (lcol == 0) {
                int rl = wm * 64 + mi * 16 + h * 8 + lrow;   // local row 0..127
                smerge[rl][wn] = make_uint4(__float_as_uint(s1), i1,
                                            __float_as_uint(s2), i2);
            }
        }

    // ---- Epilogue stage 2 (proven): merge 4 wn-tiles -> top-2 per row ----
    __syncthreads();
    if (t < BM) {
        float s1 = -CUDART_INF_F, s2 = -CUDART_INF_F;
        unsigned i1 = 0, i2 = 0;
#pragma unroll
        for (int w = 0; w < 4; w++) {            // ascending n: strict > keeps first idx
            uint4 e = smerge[t][w];
            float a1 = __uint_as_float(e.x), a2 = __uint_as_float(e.z);
            if (a1 > s1) { s2 = s1; i2 = i1; s1 = a1; i1 = e.y; }
            else if (a1 > s2) { s2 = a1; i2 = e.y; }
            if (a2 > s1) { s2 = s1; i2 = i1; s1 = a2; i1 = e.w; }
            else if (a2 > s2) { s2 = a2; i2 = e.w; }
        }
        g_cand[(size_t)(m0 + t) * CTILES + blockIdx.x] =
            make_uint4(__float_as_uint(s1), i1, __float_as_uint(s2), i2);
    }
}

// ---------------------------------------------------------------------------
// Per row: approx max over 512 candidates, fp32-rescore within MARGIN,
// exact argmax (first-index tie-break). One warp per row. (Proven code.)
// ---------------------------------------------------------------------------
__global__ void k_select(const float* __restrict__ H, const float* __restrict__ A,
                         float* __restrict__ out) {
    int r = (blockIdx.x * blockDim.x + threadIdx.x) >> 5;
    int lane = threadIdx.x & 31;
    if (r >= BQ) return;
    const uint2* cand = (const uint2*)(g_cand + (size_t)r * CTILES);  // 512 entries

    float mx = -CUDART_INF_F;
    for (int j = lane; j < CTILES * 2; j += 32)
        mx = fmaxf(mx, __uint_as_float(cand[j].x));
#pragma unroll
    for (int o = 16; o; o >>= 1) mx = fmaxf(mx, __shfl_xor_sync(0xffffffffu, mx, o));
    float thr = mx - MARGIN;

    const float4* h4 = (const float4*)(H + (size_t)r * D);
    float4 hv[4];
#pragma unroll
    for (int i = 0; i < 4; i++) hv[i] = h4[lane + 32 * i];

    unsigned long long best = 0ull;
    for (int j0 = 0; j0 < CTILES * 2; j0 += 32) {
        uint2 c = cand[j0 + lane];
        unsigned m = __ballot_sync(0xffffffffu, __uint_as_float(c.x) >= thr);
        while (m) {
            int src = __ffs(m) - 1; m &= m - 1;
            unsigned idx = __shfl_sync(0xffffffffu, c.y, src);
            const float4* a4 = (const float4*)(A + (size_t)idx * D);
            float p = 0.f;
#pragma unroll
            for (int i = 0; i < 4; i++) {
                float4 av = a4[lane + 32 * i];
                p += hv[i].x * av.x + hv[i].y * av.y + hv[i].z * av.z + hv[i].w * av.w;
            }
#pragma unroll
            for (int o = 16; o; o >>= 1) p += __shfl_xor_sync(0xffffffffu, p, o);
            float s = p * g_inv_a[idx];
            unsigned u = __float_as_uint(s);
            u = (u & 0x80000000u) ? ~u : (u | 0x80000000u);
            unsigned long long key =
                ((unsigned long long)u << 32) | (unsigned long long)(0xFFFFFFFFu - idx);
            if (key > best) best = key;
        }
    }
    if (lane == 0)
        out[r] = (float)(0xFFFFFFFFu - (unsigned)(best & 0xFFFFFFFFull));
}

// ---------------------------------------------------------------------------
extern "C" void kernel_launch(void* const* d_in, const int* in_sizes, int n_in,
                              void* d_out, int out_size) {
    const float* H = (const float*)d_in[0];
    const float* A = (const float*)d_in[1];
    if (n_in >= 2 && in_sizes[0] == A_ELEMS) {   // bind by size
        H = (const float*)d_in[1];
        A = (const float*)d_in[0];
    }

    k_prep_h<<<H_ELEMS / 2 / 256, 256>>>(H);
    k_prep_a<<<KA / 8, 256>>>(A);

    cudaFuncSetAttribute(k_gemm_bf16, cudaFuncAttributeMaxDynamicSharedMemorySize, SMEM_TOTAL);
    dim3 grid(KA / BN, BQ / BM);                 // 256 x 32 = 8192 CTAs
    k_gemm_bf16<<<grid, 256, SMEM_TOTAL>>>();

    k_select<<<BQ / 8, 256>>>(H, A, (float*)d_out);
}